// round 1
// baseline (speedup 1.0000x reference)
#include <cuda_runtime.h>
#include <stdint.h>

// Problem constants
#define NB   8
#define CIN  3
#define HW   128
#define OC   16
#define NF   27          // Cin*3*3
#define NPIX (NB*HW*HW)  // 131072 pixels
#define XN   (NB*CIN*HW*HW)

// Device scratch (allocation-free rule: __device__ globals)
__device__ __align__(16) short g_prodT[65536];        // [iw][ip] combined int16 products
__device__ int               g_wbase[NF*OC];          // [f*16+o] = (qw+128)*256
__device__ unsigned char     g_ipx[XN];               // qx+128 in [1,255]

// ---------------------------------------------------------------------------
// Prep: quantize x, quantize w, combine+transpose LUT. One launch covers all.
// ---------------------------------------------------------------------------
__global__ void prep_kernel(const float* __restrict__ x,
                            const float* __restrict__ w,
                            const float* __restrict__ sxp,
                            const float* __restrict__ swp,
                            const int*   __restrict__ lut)
{
    int i = blockIdx.x * blockDim.x + threadIdx.x;

    if (i < XN) {
        // jnp.round == rintf (round-half-even), then clip to [-127,127]
        float q = rintf(x[i] / sxp[0]);
        q = fminf(fmaxf(q, -127.0f), 127.0f);
        g_ipx[i] = (unsigned char)((int)q + 128);
    }
    if (i < 65536) {
        // source row i = ip*256 + iw ; value = hi*256 + (lo & 255) (fits int16)
        int hi = lut[2*i];
        int lo = lut[2*i + 1] & 255;
        int ip = i >> 8;
        int iw = i & 255;
        g_prodT[iw*256 + ip] = (short)(hi*256 + lo);
    }
    if (i < NF*OC) {
        // weight flat index = o*27 + f  (reshape(O, Cin*K*K))
        float q = rintf(w[i] / swp[0]);
        q = fminf(fmaxf(q, -127.0f), 127.0f);
        int iw = (int)q + 128;
        int o = i / NF;
        int f = i - o*NF;
        g_wbase[f*OC + o] = iw * 256;   // row base into g_prodT
    }
}

// ---------------------------------------------------------------------------
// Conv: 128 blocks x 1024 threads = 1 thread per (b,h,w) pixel, one wave.
// SMEM: 128KB LUT + 432 weight bases + 3x10x130 activation tile.
// ---------------------------------------------------------------------------
#define SM_PROD_BYTES 131072
#define SM_WB_BYTES   (NF*OC*4)          // 1728
#define SM_TILE_ELEMS (3*10*130)         // 3900
#define SM_TOTAL      (SM_PROD_BYTES + SM_WB_BYTES + ((SM_TILE_ELEMS + 15) & ~15))

__global__ __launch_bounds__(1024)
void conv_kernel(const float* __restrict__ bias,
                 const float* __restrict__ sxp,
                 const float* __restrict__ swp,
                 float* __restrict__ out)
{
    extern __shared__ char smem[];
    short*         sprod = (short*)smem;                              // 65536 shorts
    int*           swb   = (int*)(smem + SM_PROD_BYTES);              // 432 ints
    unsigned char* stile = (unsigned char*)(smem + SM_PROD_BYTES + SM_WB_BYTES);

    const int tid  = threadIdx.x;
    const int b    = blockIdx.x >> 4;   // batch
    const int rowg = blockIdx.x & 15;   // 8-row group within image

    // Stage the 128KB product table (int4 vector copies: 8 per thread)
    {
        const int4* src = (const int4*)g_prodT;
        int4*       dst = (int4*)sprod;
        #pragma unroll
        for (int k = 0; k < 8; k++)
            dst[tid + k*1024] = src[tid + k*1024];
    }
    if (tid < NF*OC) swb[tid] = g_wbase[tid];

    // Stage activation tile [3][10][130] with halo; out-of-image -> ip=128
    for (int t = tid; t < SM_TILE_ELEMS; t += 1024) {
        int cin = t / 1300;
        int rem = t - cin*1300;
        int rr  = rem / 130;
        int cc  = rem - rr*130;
        int hh  = rowg*8 + rr - 1;
        int ww  = cc - 1;
        unsigned char v = 128;
        if ((unsigned)hh < 128u && (unsigned)ww < 128u)
            v = g_ipx[((b*3 + cin)*128 + hh)*128 + ww];
        stile[t] = v;
    }
    __syncthreads();

    const int c = tid & 127;   // column
    const int r = tid >> 7;    // row within group

    int acc[OC];
    #pragma unroll
    for (int o = 0; o < OC; o++) acc[o] = 0;

    #pragma unroll 1
    for (int cin = 0; cin < 3; cin++) {
        #pragma unroll 1
        for (int dh = 0; dh < 3; dh++) {
            #pragma unroll
            for (int dw = 0; dw < 3; dw++) {
                const int f  = (cin*3 + dh)*3 + dw;
                const int ip = stile[cin*1300 + (r + dh)*130 + (c + dw)];
                const int* wb = &swb[f*OC];
                #pragma unroll
                for (int o = 0; o < OC; o++)
                    acc[o] += sprod[wb[o] + ip];
            }
        }
    }

    const float s = sxp[0] * swp[0];
    const int h = rowg*8 + r;
    #pragma unroll
    for (int o = 0; o < OC; o++)
        out[((b*OC + o)*128 + h)*128 + c] = (float)acc[o] * s + __ldg(&bias[o]);
}

// ---------------------------------------------------------------------------
extern "C" void kernel_launch(void* const* d_in, const int* in_sizes, int n_in,
                              void* d_out, int out_size)
{
    const float* x    = (const float*)d_in[0];
    const float* w    = (const float*)d_in[1];
    const float* bias = (const float*)d_in[2];
    const float* sx   = (const float*)d_in[3];
    const float* sw   = (const float*)d_in[4];
    const int*   lut  = (const int*)d_in[5];
    float* out = (float*)d_out;

    cudaFuncSetAttribute(conv_kernel,
                         cudaFuncAttributeMaxDynamicSharedMemorySize, SM_TOTAL);

    prep_kernel<<<(XN + 255) / 256, 256>>>(x, w, sx, sw, lut);
    conv_kernel<<<NB * 16, 1024, SM_TOTAL>>>(bias, sx, sw, out);
}

// round 2
// speedup vs baseline: 1.1099x; 1.1099x over previous
#include <cuda_runtime.h>
#include <stdint.h>

// Problem constants
#define NB   8
#define CIN  3
#define HW   128
#define OC   16
#define NF   27          // Cin*3*3
#define XN   (NB*CIN*HW*HW)

// Device scratch (allocation-free rule: __device__ globals)
__device__ int               g_qw[NF*OC];             // [o*27+f] = qw+128
__device__ __align__(16) short g_prodF[NF*256*OC];    // [f][ip][o] int16 products (216KB)
__device__ unsigned char     g_ipx[XN];               // qx+128 in [1,255]

// ---------------------------------------------------------------------------
// Prep1: quantize activations and weights.
// ---------------------------------------------------------------------------
__global__ void prep1_kernel(const float* __restrict__ x,
                             const float* __restrict__ w,
                             const float* __restrict__ sxp,
                             const float* __restrict__ swp)
{
    int i = blockIdx.x * blockDim.x + threadIdx.x;

    if (i < XN) {
        float q = rintf(x[i] / sxp[0]);          // round-half-even like jnp.round
        q = fminf(fmaxf(q, -127.0f), 127.0f);
        g_ipx[i] = (unsigned char)((int)q + 128);
    }
    if (i < NF*OC) {
        float q = rintf(w[i] / swp[0]);          // flat idx = o*27 + f
        q = fminf(fmaxf(q, -127.0f), 127.0f);
        g_qw[i] = (int)q + 128;
    }
}

// ---------------------------------------------------------------------------
// Prep2: build packed per-tap channel table prodF[f][ip][o].
// value = hi*256 + (lo & 255) from lut row ip*256 + iw  (fits int16 exactly)
// ---------------------------------------------------------------------------
__global__ void prep2_kernel(const int* __restrict__ lut)
{
    int idx = blockIdx.x * blockDim.x + threadIdx.x;   // 27*256*16 = 110592
    if (idx >= NF*256*OC) return;
    int o  = idx & 15;
    int ip = (idx >> 4) & 255;
    int f  = idx >> 12;
    int iw = g_qw[o*NF + f];
    int row = ip*256 + iw;
    int hi = lut[2*row];
    int lo = lut[2*row + 1] & 255;
    g_prodF[(f*256 + ip)*OC + o] = (short)(hi*256 + lo);
}

// ---------------------------------------------------------------------------
// Conv: 128 blocks x 1024 threads = 1 thread per (b,h,w) pixel, one wave.
// SMEM: 216KB packed table + 3x10x130 activation tile.
// Per tap: 2x LDS.128 fetches all 16 channel products at once.
// ---------------------------------------------------------------------------
#define SM_PROD_BYTES (NF*256*OC*2)      // 221184
#define SM_TILE_ELEMS (3*10*130)         // 3900
#define SM_TOTAL      (SM_PROD_BYTES + ((SM_TILE_ELEMS + 15) & ~15))

__global__ __launch_bounds__(1024)
void conv_kernel(const float* __restrict__ bias,
                 const float* __restrict__ sxp,
                 const float* __restrict__ swp,
                 float* __restrict__ out)
{
    extern __shared__ char smem[];
    unsigned char* stile = (unsigned char*)(smem + SM_PROD_BYTES);

    const int tid  = threadIdx.x;
    const int b    = blockIdx.x >> 4;   // batch
    const int rowg = blockIdx.x & 15;   // 8-row group within image

    // Stage the 216KB packed table (int4 vector copies)
    {
        const int4* src = (const int4*)g_prodF;
        int4*       dst = (int4*)smem;
        #pragma unroll
        for (int k = 0; k < 14; k++) {
            int idx = tid + k*1024;
            if (idx < SM_PROD_BYTES/16) dst[idx] = src[idx];
        }
    }

    // Stage activation tile [3][10][130] with halo; out-of-image -> ip=128
    for (int t = tid; t < SM_TILE_ELEMS; t += 1024) {
        int cin = t / 1300;
        int rem = t - cin*1300;
        int rr  = rem / 130;
        int cc  = rem - rr*130;
        int hh  = rowg*8 + rr - 1;
        int ww  = cc - 1;
        unsigned char v = 128;
        if ((unsigned)hh < 128u && (unsigned)ww < 128u)
            v = g_ipx[((b*3 + cin)*128 + hh)*128 + ww];
        stile[t] = v;
    }
    __syncthreads();

    const int c = tid & 127;   // column
    const int r = tid >> 7;    // row within 8-row group

    int acc[OC];
    #pragma unroll
    for (int o = 0; o < OC; o++) acc[o] = 0;

    #pragma unroll 1
    for (int cin = 0; cin < 3; cin++) {
        #pragma unroll 1
        for (int dh = 0; dh < 3; dh++) {
            const unsigned char* trow = &stile[cin*1300 + (r + dh)*130 + c];
            #pragma unroll
            for (int dw = 0; dw < 3; dw++) {
                const int f  = (cin*3 + dh)*3 + dw;
                const int ip = trow[dw];
                const uint4* p = (const uint4*)(smem + (f*256 + ip)*32);
                uint4 a = p[0];
                uint4 bq = p[1];
                // unpack 16 shorts -> 16 int accumulators
                acc[ 0] += (int)(short)(a.x & 0xFFFF);  acc[ 1] += ((int)a.x)  >> 16;
                acc[ 2] += (int)(short)(a.y & 0xFFFF);  acc[ 3] += ((int)a.y)  >> 16;
                acc[ 4] += (int)(short)(a.z & 0xFFFF);  acc[ 5] += ((int)a.z)  >> 16;
                acc[ 6] += (int)(short)(a.w & 0xFFFF);  acc[ 7] += ((int)a.w)  >> 16;
                acc[ 8] += (int)(short)(bq.x & 0xFFFF); acc[ 9] += ((int)bq.x) >> 16;
                acc[10] += (int)(short)(bq.y & 0xFFFF); acc[11] += ((int)bq.y) >> 16;
                acc[12] += (int)(short)(bq.z & 0xFFFF); acc[13] += ((int)bq.z) >> 16;
                acc[14] += (int)(short)(bq.w & 0xFFFF); acc[15] += ((int)bq.w) >> 16;
            }
        }
    }

    const float s = sxp[0] * swp[0];
    const int h = rowg*8 + r;
    #pragma unroll
    for (int o = 0; o < OC; o++)
        out[((b*OC + o)*128 + h)*128 + c] = (float)acc[o] * s + __ldg(&bias[o]);
}

// ---------------------------------------------------------------------------
extern "C" void kernel_launch(void* const* d_in, const int* in_sizes, int n_in,
                              void* d_out, int out_size)
{
    const float* x    = (const float*)d_in[0];
    const float* w    = (const float*)d_in[1];
    const float* bias = (const float*)d_in[2];
    const float* sx   = (const float*)d_in[3];
    const float* sw   = (const float*)d_in[4];
    const int*   lut  = (const int*)d_in[5];
    float* out = (float*)d_out;

    cudaFuncSetAttribute(conv_kernel,
                         cudaFuncAttributeMaxDynamicSharedMemorySize, SM_TOTAL);

    prep1_kernel<<<(XN + 255) / 256, 256>>>(x, w, sx, sw);
    prep2_kernel<<<(NF*256*OC + 255) / 256, 256>>>(lut);
    conv_kernel<<<NB * 16, 1024, SM_TOTAL>>>(bias, sx, sw, out);
}

// round 3
// speedup vs baseline: 1.4009x; 1.2622x over previous
#include <cuda_runtime.h>
#include <stdint.h>

// Problem constants
#define NB   8
#define CIN  3
#define HW   128
#define OC   16
#define NF   27          // Cin*3*3

// Device scratch: two half-tables, 16B rows (8 channels each).
// Row stride 16B -> LDS.128 start slot = (4*ip) mod 32 -> 8 distinct slots.
__device__ __align__(16) short g_prodA[NF*256*8];   // [f][ip][o:0-7]   108KB
__device__ __align__(16) short g_prodB[NF*256*8];   // [f][ip][o:8-15]  108KB

// ---------------------------------------------------------------------------
// Table builder: one thread per (f, ip, o). Quantizes its weight inline
// (redundant but removes a kernel + dependency), gathers lut pair, writes
// combined int16 product into the split tables.
// ---------------------------------------------------------------------------
__global__ void prep_table(const float* __restrict__ w,
                           const float* __restrict__ swp,
                           const int*   __restrict__ lut)
{
    int idx = blockIdx.x * blockDim.x + threadIdx.x;   // 27*256*16 = 110592
    if (idx >= NF*256*OC) return;
    int o  = idx & 15;
    int ip = (idx >> 4) & 255;
    int f  = idx >> 12;

    float q = rintf(w[o*NF + f] / swp[0]);   // round-half-even like jnp.round
    q = fminf(fmaxf(q, -127.0f), 127.0f);
    int iw = (int)q + 128;

    int row = ip*256 + iw;
    int2 hl = ((const int2*)lut)[row];       // (hi, lo)
    short v = (short)(hl.x*256 + (hl.y & 255));

    if (o < 8) g_prodA[(f*256 + ip)*8 + o]     = v;
    else       g_prodB[(f*256 + ip)*8 + (o-8)] = v;
}

// ---------------------------------------------------------------------------
// Conv: 128 blocks x 1024 threads = 1 thread per (b,h,w) pixel, one wave.
// SMEM: 2x108KB split tables + 3x10x130 quantized activation tile.
// Per tap: 2x LDS.128 (one per half-table), 8-slot bank distribution.
// Activations quantized inline during tile staging (no separate prep pass).
// ---------------------------------------------------------------------------
#define SM_A_BYTES   (NF*256*8*2)        // 110592
#define SM_AB_BYTES  (2*SM_A_BYTES)      // 221184
#define SM_TILE_ELEMS (3*10*130)         // 3900
#define SM_TOTAL     (SM_AB_BYTES + ((SM_TILE_ELEMS + 15) & ~15))

__global__ __launch_bounds__(1024)
void conv_kernel(const float* __restrict__ x,
                 const float* __restrict__ bias,
                 const float* __restrict__ sxp,
                 const float* __restrict__ swp,
                 float* __restrict__ out)
{
    extern __shared__ char smem[];
    unsigned char* stile = (unsigned char*)(smem + SM_AB_BYTES);

    const int tid  = threadIdx.x;
    const int b    = blockIdx.x >> 4;   // batch
    const int rowg = blockIdx.x & 15;   // 8-row group within image

    // Stage both half-tables (216KB) with int4 vector copies
    {
        const int4* srcA = (const int4*)g_prodA;
        const int4* srcB = (const int4*)g_prodB;
        int4* dstA = (int4*)smem;
        int4* dstB = (int4*)(smem + SM_A_BYTES);
        #pragma unroll
        for (int k = 0; k < 6; k++) {
            dstA[tid + k*1024] = srcA[tid + k*1024];
            dstB[tid + k*1024] = srcB[tid + k*1024];
        }
        if (tid < (SM_A_BYTES/16 - 6*1024)) {           // 6912 - 6144 = 768
            dstA[tid + 6*1024] = srcA[tid + 6*1024];
            dstB[tid + 6*1024] = srcB[tid + 6*1024];
        }
    }

    // Stage + quantize activation tile [3][10][130]; out-of-image -> ip=128
    {
        const float sx = sxp[0];
        for (int t = tid; t < SM_TILE_ELEMS; t += 1024) {
            int cin = t / 1300;
            int rem = t - cin*1300;
            int rr  = rem / 130;
            int cc  = rem - rr*130;
            int hh  = rowg*8 + rr - 1;
            int ww  = cc - 1;
            unsigned char v = 128;
            if ((unsigned)hh < 128u && (unsigned)ww < 128u) {
                float xf = x[((b*3 + cin)*128 + hh)*128 + ww];
                float q = rintf(xf / sx);                 // round-half-even
                q = fminf(fmaxf(q, -127.0f), 127.0f);
                v = (unsigned char)((int)q + 128);
            }
            stile[t] = v;
        }
    }
    __syncthreads();

    const int c = tid & 127;   // column
    const int r = tid >> 7;    // row within 8-row group

    int acc[OC];
    #pragma unroll
    for (int o = 0; o < OC; o++) acc[o] = 0;

    const uint4* TA = (const uint4*)smem;
    const uint4* TB = (const uint4*)(smem + SM_A_BYTES);

    #pragma unroll 1
    for (int cin = 0; cin < 3; cin++) {
        #pragma unroll 1
        for (int dh = 0; dh < 3; dh++) {
            const unsigned char* trow = &stile[cin*1300 + (r + dh)*130 + c];
            #pragma unroll
            for (int dw = 0; dw < 3; dw++) {
                const int f   = (cin*3 + dh)*3 + dw;
                const int idx = f*256 + (int)trow[dw];
                uint4 a  = TA[idx];
                uint4 bq = TB[idx];
                // unpack 16 shorts -> 16 int accumulators
                acc[ 0] += (int)(short)(a.x & 0xFFFF);  acc[ 1] += ((int)a.x)  >> 16;
                acc[ 2] += (int)(short)(a.y & 0xFFFF);  acc[ 3] += ((int)a.y)  >> 16;
                acc[ 4] += (int)(short)(a.z & 0xFFFF);  acc[ 5] += ((int)a.z)  >> 16;
                acc[ 6] += (int)(short)(a.w & 0xFFFF);  acc[ 7] += ((int)a.w)  >> 16;
                acc[ 8] += (int)(short)(bq.x & 0xFFFF); acc[ 9] += ((int)bq.x) >> 16;
                acc[10] += (int)(short)(bq.y & 0xFFFF); acc[11] += ((int)bq.y) >> 16;
                acc[12] += (int)(short)(bq.z & 0xFFFF); acc[13] += ((int)bq.z) >> 16;
                acc[14] += (int)(short)(bq.w & 0xFFFF); acc[15] += ((int)bq.w) >> 16;
            }
        }
    }

    const float s = sxp[0] * swp[0];
    const int h = rowg*8 + r;
    #pragma unroll
    for (int o = 0; o < OC; o++)
        out[((b*OC + o)*128 + h)*128 + c] = (float)acc[o] * s + __ldg(&bias[o]);
}

// ---------------------------------------------------------------------------
extern "C" void kernel_launch(void* const* d_in, const int* in_sizes, int n_in,
                              void* d_out, int out_size)
{
    const float* x    = (const float*)d_in[0];
    const float* w    = (const float*)d_in[1];
    const float* bias = (const float*)d_in[2];
    const float* sx   = (const float*)d_in[3];
    const float* sw   = (const float*)d_in[4];
    const int*   lut  = (const int*)d_in[5];
    float* out = (float*)d_out;

    cudaFuncSetAttribute(conv_kernel,
                         cudaFuncAttributeMaxDynamicSharedMemorySize, SM_TOTAL);

    prep_table<<<(NF*256*OC + 255) / 256, 256>>>(w, sw, lut);
    conv_kernel<<<NB * 16, 1024, SM_TOTAL>>>(x, bias, sx, sw, out);
}